// round 14
// baseline (speedup 1.0000x reference)
#include <cuda_runtime.h>
#include <cuda_fp16.h>
#include <math.h>
#include <stdint.h>

#define NN 50000
#define EE 800000
#define DD 2048
#define CC 256
#define ESL (EE + NN)

// ---------------- scratch (static device globals; no runtime alloc) --------
__device__ __half g_hA[NN * CC];     // h1_pre (fp16)
__device__ __half g_hB[NN * CC];     // h1
__device__ __half g_hC[NN * CC];     // h2_pre
__device__ __half g_hD[NN * CC];     // h2
__device__ __half g_uv[NN * 512];    // [u | v] per node (fp16)
__device__ __half g_Bf[512 * 2048];  // packed weights: W1 | W2 | Wp1
__device__ float g_s[NN];
__device__ float g_t[NN];
__device__ int   g_deg[NN];
__device__ int   g_off[NN + 1];
__device__ int   g_cursor[NN];
__device__ int   g_csrc[ESL];

#define BF_W1_OFF 0
#define BF_W2_OFF (256 * 2048)
#define BF_WP_OFF (256 * 2048 + 256 * 256)
#define BF_TOTAL  (256 * 2048 + 256 * 256 + 512 * 256)

// ================= helpers ==================================================
__device__ __forceinline__ uint32_t smem_u32(const void* p) {
    uint32_t a;
    asm("{ .reg .u64 t; cvta.to.shared.u64 t, %1; cvt.u32.u64 %0, t; }"
        : "=r"(a) : "l"(p));
    return a;
}

#define LDSM4(r, addr) \
    asm volatile("ldmatrix.sync.aligned.m8n8.x4.shared.b16 {%0,%1,%2,%3}, [%4];" \
        : "=r"((r)[0]), "=r"((r)[1]), "=r"((r)[2]), "=r"((r)[3]) : "r"(addr))

#define MMA16816(c, a, b0, b1) \
    asm volatile("mma.sync.aligned.m16n8k16.row.col.f32.f16.f16.f32 " \
        "{%0,%1,%2,%3}, {%4,%5,%6,%7}, {%8,%9}, {%0,%1,%2,%3};" \
        : "+f"((c)[0]), "+f"((c)[1]), "+f"((c)[2]), "+f"((c)[3]) \
        : "r"((a)[0]), "r"((a)[1]), "r"((a)[2]), "r"((a)[3]), "r"(b0), "r"(b1))

#define CP_ASYNC16(smem, gptr) \
    asm volatile("cp.async.cg.shared.global [%0], [%1], 16;" \
        :: "r"(smem), "l"(gptr) : "memory")
#define CP_COMMIT() asm volatile("cp.async.commit_group;" ::: "memory")
#define CP_WAIT1()  asm volatile("cp.async.wait_group 1;" ::: "memory")

// ---------------- CSR build -------------------------------------------------
__global__ void count_kernel(const int* __restrict__ dst, int* deg, int E) {
    int i = blockIdx.x * blockDim.x + threadIdx.x;
    if (i < E) atomicAdd(&deg[dst[i]], 1);
}

// tiled coalesced single-block exclusive scan; adds +1 per node (self loop)
// and fuses the selfloop placement (csrc[off]=i, cursor=off+1)
__global__ void scan_kernel(const int* __restrict__ deg, int* __restrict__ off,
                            int* __restrict__ cursor, int* __restrict__ csrc, int n) {
    __shared__ int warp_sums[32];
    const int tid  = threadIdx.x;
    const int lane = tid & 31;
    const int w    = tid >> 5;
    int carry = 0;
    for (int base = 0; base < n; base += 1024) {
        int i = base + tid;
        int v = (i < n) ? (deg[i] + 1) : 0;
        int x = v;
        #pragma unroll
        for (int o = 1; o < 32; o <<= 1) {
            int y = __shfl_up_sync(0xffffffffu, x, o);
            if (lane >= o) x += y;
        }
        if (lane == 31) warp_sums[w] = x;
        __syncthreads();
        if (w == 0) {
            int s = warp_sums[lane];
            #pragma unroll
            for (int o = 1; o < 32; o <<= 1) {
                int y = __shfl_up_sync(0xffffffffu, s, o);
                if (lane >= o) s += y;
            }
            warp_sums[lane] = s;
        }
        __syncthreads();
        int incl = x + (w > 0 ? warp_sums[w - 1] : 0);
        int total = warp_sums[31];
        if (i < n) {
            int o = carry + incl - v;
            off[i] = o;
            csrc[o] = i;           // self loop first (deterministic slot)
            cursor[i] = o + 1;
        }
        carry += total;
        __syncthreads();
    }
    if (tid == 0) off[n] = carry;
}

__global__ void scatter_kernel(const int* __restrict__ src, const int* __restrict__ dst,
                               int* cursor, int* csrc, int E) {
    int i = blockIdx.x * blockDim.x + threadIdx.x;
    if (i < E) {
        int d = dst[i];
        int p = atomicAdd(&cursor[d], 1);
        csrc[p] = src[i];
    }
}

// ---------------- mega-pack: W1, W2, Wp1 -> g_Bf fp16 [N,K] -----------------
__global__ void mega_pack_kernel(const float* __restrict__ W1,
                                 const float* __restrict__ W2,
                                 const float* __restrict__ Wp1,
                                 __half* __restrict__ Bf) {
    int i = blockIdx.x * blockDim.x + threadIdx.x;
    if (i >= BF_TOTAL) return;
    if (i < BF_W2_OFF) {
        int n = i >> 11, k = i & 2047;
        Bf[i] = __float2half_rn(W1[(size_t)k * 256 + n]);
    } else if (i < BF_WP_OFF) {
        int j = i - BF_W2_OFF;
        int n = j >> 8, k = j & 255;
        Bf[i] = __float2half_rn(W2[(size_t)k * 256 + n]);
    } else {
        int j = i - BF_WP_OFF;
        int n = j >> 8, k = j & 255;
        int srcRow = (n < 256) ? k : (256 + k);
        int srcCol = (n < 256) ? n : (n - 256);
        Bf[i] = __float2half_rn(Wp1[(size_t)srcRow * 256 + srcCol]);
    }
}

// ---------------- mma.sync fp16 GEMM framework (BK=64) ----------------------
#define GBM 128
#define GBN 256
#define GBK 64
#define NSTG 3
#define LDAB 72
#define A_MAT (128 * LDAB * 2)         // 18432
#define B_MAT (256 * LDAB * 2)         // 36864
#define AH_OFF 0
#define BF_OFF A_MAT
#define STG_STAGE (A_MAT + B_MAT)      // 55296

#define EPILOGUE_FP16()                                                        \
    _Pragma("unroll")                                                          \
    for (int i = 0; i < 4; ++i) {                                              \
        int row0 = brow + wm + i * 16 + (lane >> 2);                           \
        _Pragma("unroll")                                                      \
        for (int j = 0; j < 8; ++j) {                                          \
            int col = bcol + wn + j * 8 + (lane & 3) * 2;                      \
            if (row0 < M) {                                                    \
                __half2 v = __floats2half2_rn(acc[i][j][0], acc[i][j][1]);     \
                *(__half2*)(C16 + (size_t)row0 * Nout + col) = v;              \
            }                                                                  \
            if (row0 + 8 < M) {                                                \
                __half2 v = __floats2half2_rn(acc[i][j][2], acc[i][j][3]);     \
                *(__half2*)(C16 + (size_t)(row0 + 8) * Nout + col) = v;        \
            }                                                                  \
        }                                                                      \
    }

// fused per-row attention dots from the fp32 accumulators (only when the CTA
// covers the full 256-col row: Nout==256, bcol==0). smem reused as [s|t][128].
#define EPILOGUE_DOTS()                                                        \
    if (dots_s) {                                                              \
        float* sd = (float*)sm;                                                \
        float* td = (float*)sm + 128;                                          \
        __syncthreads();                                                       \
        if (tid < 256) ((float*)sm)[tid] = 0.f;                                \
        __syncthreads();                                                       \
        _Pragma("unroll")                                                      \
        for (int i = 0; i < 4; ++i) {                                          \
            float ps0 = 0.f, pt0 = 0.f, ps1 = 0.f, pt1 = 0.f;                  \
            _Pragma("unroll")                                                  \
            for (int j = 0; j < 8; ++j) {                                      \
                int col = wn + j * 8 + (lane & 3) * 2;                         \
                float a0 = dots_asrc[col], a1 = dots_asrc[col + 1];            \
                float d0 = dots_adst[col], d1 = dots_adst[col + 1];            \
                ps0 += acc[i][j][0] * a0 + acc[i][j][1] * a1;                  \
                pt0 += acc[i][j][0] * d0 + acc[i][j][1] * d1;                  \
                ps1 += acc[i][j][2] * a0 + acc[i][j][3] * a1;                  \
                pt1 += acc[i][j][2] * d0 + acc[i][j][3] * d1;                  \
            }                                                                  \
            ps0 += __shfl_xor_sync(0xffffffffu, ps0, 1);                       \
            ps0 += __shfl_xor_sync(0xffffffffu, ps0, 2);                       \
            pt0 += __shfl_xor_sync(0xffffffffu, pt0, 1);                       \
            pt0 += __shfl_xor_sync(0xffffffffu, pt0, 2);                       \
            ps1 += __shfl_xor_sync(0xffffffffu, ps1, 1);                       \
            ps1 += __shfl_xor_sync(0xffffffffu, ps1, 2);                       \
            pt1 += __shfl_xor_sync(0xffffffffu, pt1, 1);                       \
            pt1 += __shfl_xor_sync(0xffffffffu, pt1, 2);                       \
            if ((lane & 3) == 0) {                                             \
                int r = wm + i * 16 + (lane >> 2);                             \
                atomicAdd(&sd[r], ps0);     atomicAdd(&td[r], pt0);            \
                atomicAdd(&sd[r + 8], ps1); atomicAdd(&td[r + 8], pt1);        \
            }                                                                  \
        }                                                                      \
        __syncthreads();                                                       \
        if (tid < 128) {                                                       \
            int row = brow + tid;                                              \
            if (row < M) { dots_s[row] = sd[tid]; dots_t[row] = td[tid]; }     \
        }                                                                      \
    }

#define GEMM_COMPUTE_BODY()                                                    \
    auto COMPUTE = [&](int t) {                                                \
        const uint32_t base = sb + (uint32_t)(t % NSTG) * STG_STAGE;           \
        _Pragma("unroll")                                                      \
        for (int ks = 0; ks < 4; ++ks) {                                       \
            const uint32_t coff = (uint32_t)(ks * 16 + lcol * 8) * 2;          \
            uint32_t bf[4][4], af[4][4];                                       \
            _Pragma("unroll")                                                  \
            for (int g = 0; g < 4; ++g) {                                      \
                uint32_t addr = base + (uint32_t)((wn + g * 16 + lrow) * LDAB) * 2 + coff; \
                LDSM4(bf[g], addr + BF_OFF);                                   \
            }                                                                  \
            _Pragma("unroll")                                                  \
            for (int i = 0; i < 4; ++i) {                                      \
                uint32_t aaddr = base + (uint32_t)((wm + i * 16 + lrow) * LDAB) * 2 + coff; \
                LDSM4(af[i], aaddr + AH_OFF);                                  \
            }                                                                  \
            _Pragma("unroll")                                                  \
            for (int i = 0; i < 4; ++i)                                        \
                _Pragma("unroll")                                              \
                for (int j = 0; j < 8; ++j) {                                  \
                    int g = j >> 1, sel = j & 1;                               \
                    MMA16816(acc[i][j], af[i], bf[g][sel], bf[g][sel + 2]);    \
                }                                                              \
        }                                                                      \
    };

// --- variant 1: A fp32 (converted in-kernel), used for GEMM1 only -----------
__global__ void __launch_bounds__(256, 1)
mma_gemm_a32_kernel(const float* __restrict__ A,
                    const __half* __restrict__ Bfp,
                    __half* __restrict__ C16, int M, int Ktot, int Nout,
                    const float* __restrict__ dots_asrc,
                    const float* __restrict__ dots_adst,
                    float* __restrict__ dots_s, float* __restrict__ dots_t)
{
    extern __shared__ char sm[];
    const uint32_t sb = smem_u32(sm);

    const int tid  = threadIdx.x;
    const int wid  = tid >> 5;
    const int lane = tid & 31;
    const int brow = blockIdx.y * GBM;
    const int bcol = blockIdx.x * GBN;
    const int wm   = (wid & 1) * 64;
    const int wn   = (wid >> 1) * 64;

    float acc[4][8][4];
    #pragma unroll
    for (int i = 0; i < 4; i++)
        #pragma unroll
        for (int j = 0; j < 8; j++)
            #pragma unroll
            for (int r = 0; r < 4; r++) acc[i][j][r] = 0.f;

    const int T = Ktot / GBK;

    auto ISSUE_B = [&](int t) {
        const int kt = t * GBK;
        const uint32_t stage = sb + (uint32_t)(t % NSTG) * STG_STAGE;
        #pragma unroll
        for (int it = 0; it < 8; ++it) {
            int idx = tid + it * 256;
            int rr  = idx >> 3;
            int cc  = idx & 7;
            uint64_t g = __cvta_generic_to_global(
                Bfp + (size_t)(bcol + rr) * Ktot + kt + cc * 8);
            uint32_t sa = stage + (uint32_t)BF_OFF
                        + (uint32_t)rr * (LDAB * 2) + (uint32_t)cc * 16;
            CP_ASYNC16(sa, g);
        }
        CP_COMMIT();
    };

    float4 pa[8];
    auto LOAD_A = [&](int t) {
        const int kt = t * GBK;
        #pragma unroll
        for (int it = 0; it < 8; ++it) {
            int idx = tid + it * 256;
            int r = idx >> 4, c4 = (idx & 15) * 4;
            pa[it] = (brow + r < M)
                ? *(const float4*)(A + (size_t)(brow + r) * Ktot + kt + c4)
                : make_float4(0.f, 0.f, 0.f, 0.f);
        }
    };

    auto STORE_A = [&](int t) {
        char* st = sm + (t % NSTG) * STG_STAGE;
        #pragma unroll
        for (int it = 0; it < 8; ++it) {
            int idx = tid + it * 256;
            int r = idx >> 4, c4 = (idx & 15) * 4;
            float4 v = pa[it];
            __half2 h01 = __floats2half2_rn(v.x, v.y);
            __half2 h23 = __floats2half2_rn(v.z, v.w);
            uint2 hp;
            hp.x = *(uint32_t*)&h01;
            hp.y = *(uint32_t*)&h23;
            uint32_t off = (uint32_t)(r * LDAB + c4) * 2;
            *(uint2*)(st + AH_OFF + off) = hp;
        }
    };

    const int lrow = lane & 15;
    const int lcol = (lane >> 4) & 1;

    GEMM_COMPUTE_BODY()

    ISSUE_B(0);
    ISSUE_B(1);
    LOAD_A(0);
    STORE_A(0);
    LOAD_A(1);

    for (int t = 0; t < T; ++t) {
        CP_WAIT1();
        __syncthreads();
        if (t + 1 < T) STORE_A(t + 1);
        if (t + 2 < T) { ISSUE_B(t + 2); LOAD_A(t + 2); }
        COMPUTE(t);
    }

    EPILOGUE_FP16()
    EPILOGUE_DOTS()
}

// --- variant 2: A fp16 via cp.async (GEMM2, uv GEMM) ------------------------
__global__ void __launch_bounds__(256, 1)
mma_gemm_a16_kernel(const __half* __restrict__ A16,
                    const __half* __restrict__ Bfp,
                    __half* __restrict__ C16, int M, int Ktot, int Nout,
                    const float* __restrict__ dots_asrc,
                    const float* __restrict__ dots_adst,
                    float* __restrict__ dots_s, float* __restrict__ dots_t)
{
    extern __shared__ char sm[];
    const uint32_t sb = smem_u32(sm);

    const int tid  = threadIdx.x;
    const int wid  = tid >> 5;
    const int lane = tid & 31;
    const int brow = blockIdx.y * GBM;
    const int bcol = blockIdx.x * GBN;
    const int wm   = (wid & 1) * 64;
    const int wn   = (wid >> 1) * 64;

    float acc[4][8][4];
    #pragma unroll
    for (int i = 0; i < 4; i++)
        #pragma unroll
        for (int j = 0; j < 8; j++)
            #pragma unroll
            for (int r = 0; r < 4; r++) acc[i][j][r] = 0.f;

    const int T = Ktot / GBK;

    auto ISSUE_AB = [&](int t) {
        const int kt = t * GBK;
        const uint32_t stage = sb + (uint32_t)(t % NSTG) * STG_STAGE;
        #pragma unroll
        for (int it = 0; it < 4; ++it) {
            int idx = tid + it * 256;
            int rr = idx >> 3;
            int cc = idx & 7;
            int row = brow + rr; if (row >= M) row = M - 1;
            uint64_t g = __cvta_generic_to_global(
                A16 + (size_t)row * Ktot + kt + cc * 8);
            uint32_t sa = stage + (uint32_t)AH_OFF
                        + (uint32_t)rr * (LDAB * 2) + (uint32_t)cc * 16;
            CP_ASYNC16(sa, g);
        }
        #pragma unroll
        for (int it = 0; it < 8; ++it) {
            int idx = tid + it * 256;
            int rr  = idx >> 3;
            int cc  = idx & 7;
            uint64_t g = __cvta_generic_to_global(
                Bfp + (size_t)(bcol + rr) * Ktot + kt + cc * 8);
            uint32_t sa = stage + (uint32_t)BF_OFF
                        + (uint32_t)rr * (LDAB * 2) + (uint32_t)cc * 16;
            CP_ASYNC16(sa, g);
        }
        CP_COMMIT();
    };

    const int lrow = lane & 15;
    const int lcol = (lane >> 4) & 1;

    GEMM_COMPUTE_BODY()

    ISSUE_AB(0);
    ISSUE_AB(1);

    for (int t = 0; t < T; ++t) {
        CP_WAIT1();
        __syncthreads();
        if (t + 2 < T) ISSUE_AB(t + 2);
        COMPUTE(t);
    }

    EPILOGUE_FP16()
    EPILOGUE_DOTS()
}

// ---------------- single-pass softmax aggregation (grid-stride warps) -------
__global__ void gat_agg_kernel(const __half* __restrict__ h,
                               const float* __restrict__ s,
                               const float* __restrict__ t,
                               const int* __restrict__ off,
                               const int* __restrict__ csrc,
                               const float* __restrict__ bias,
                               __half* __restrict__ out, int n)
{
    int gw   = (blockIdx.x * blockDim.x + threadIdx.x) >> 5;
    int nwp  = (gridDim.x * blockDim.x) >> 5;
    int lane = threadIdx.x & 31;
    float4 b0 = *(const float4*)(bias + lane * 8);
    float4 b1 = *(const float4*)(bias + lane * 8 + 4);

    for (int node = gw; node < n; node += nwp) {
        int beg = off[node], end = off[node + 1];
        float tv = t[node];
        float d = 0.f;
        float acc[8];
        #pragma unroll
        for (int q = 0; q < 8; q++) acc[q] = 0.f;

        for (int p = beg; p < end; ++p) {
            int src = csrc[p];
            float e = s[src] + tv;
            e = (e > 0.f) ? e : 0.2f * e;
            float w = __expf(e);
            d += w;
            uint4 hv = *(const uint4*)(h + (size_t)src * CC + lane * 8);
            const __half2* hh = (const __half2*)&hv;
            #pragma unroll
            for (int q = 0; q < 4; q++) {
                float2 f = __half22float2(hh[q]);
                acc[2 * q]     += w * f.x;
                acc[2 * q + 1] += w * f.y;
            }
        }

        float inv = 1.f / (d + 1e-16f);
        __half2 o_[4];
        o_[0] = __floats2half2_rn(acc[0] * inv + b0.x, acc[1] * inv + b0.y);
        o_[1] = __floats2half2_rn(acc[2] * inv + b0.z, acc[3] * inv + b0.w);
        o_[2] = __floats2half2_rn(acc[4] * inv + b1.x, acc[5] * inv + b1.y);
        o_[3] = __floats2half2_rn(acc[6] * inv + b1.z, acc[7] * inv + b1.w);
        *(uint4*)(out + (size_t)node * CC + lane * 8) = *(uint4*)o_;
    }
}

// ---------------- edge predictor (grid-stride warps, hoisted constants) -----
__global__ void edge_pred_kernel(const __half* __restrict__ uv,
                                 const int* __restrict__ esrc, const int* __restrict__ edst,
                                 const float* __restrict__ bp1, const float* __restrict__ wp2,
                                 const float* __restrict__ bp2, float* __restrict__ out, int E)
{
    int gw   = (blockIdx.x * blockDim.x + threadIdx.x) >> 5;
    int nwp  = (gridDim.x * blockDim.x) >> 5;
    int lane = threadIdx.x & 31;
    float4 b0 = *(const float4*)(bp1 + lane * 8);
    float4 b1 = *(const float4*)(bp1 + lane * 8 + 4);
    float4 w0 = *(const float4*)(wp2 + lane * 8);
    float4 w1 = *(const float4*)(wp2 + lane * 8 + 4);
    float bb[8] = {b0.x, b0.y, b0.z, b0.w, b1.x, b1.y, b1.z, b1.w};
    float ww[8] = {w0.x, w0.y, w0.z, w0.w, w1.x, w1.y, w1.z, w1.w};
    float bias2 = bp2[0];

    for (int e = gw; e < E; e += nwp) {
        int sI = esrc[e], dI = edst[e];
        uint4 uu = *(const uint4*)(uv + (size_t)sI * 512 + lane * 8);
        uint4 vv = *(const uint4*)(uv + (size_t)dI * 512 + 256 + lane * 8);
        const __half2* u2 = (const __half2*)&uu;
        const __half2* v2 = (const __half2*)&vv;
        float sum = 0.f;
        #pragma unroll
        for (int q = 0; q < 4; q++) {
            float2 fu = __half22float2(u2[q]);
            float2 fv = __half22float2(v2[q]);
            float r0 = fmaxf(fu.x + fv.x + bb[2 * q], 0.f);
            float r1 = fmaxf(fu.y + fv.y + bb[2 * q + 1], 0.f);
            sum += r0 * ww[2 * q] + r1 * ww[2 * q + 1];
        }
        #pragma unroll
        for (int o = 16; o > 0; o >>= 1) sum += __shfl_down_sync(0xffffffffu, sum, o);
        if (lane == 0) out[e] = sum + bias2;
    }
}

// ---------------- host driver -----------------------------------------------
extern "C" void kernel_launch(void* const* d_in, const int* in_sizes, int n_in,
                              void* d_out, int out_size)
{
    const float* x      = (const float*)d_in[0];
    const int*   ei     = (const int*)  d_in[1];
    const float* W1     = (const float*)d_in[2];
    const float* a_src1 = (const float*)d_in[3];
    const float* a_dst1 = (const float*)d_in[4];
    const float* b1     = (const float*)d_in[5];
    const float* W2     = (const float*)d_in[6];
    const float* a_src2 = (const float*)d_in[7];
    const float* a_dst2 = (const float*)d_in[8];
    const float* b2     = (const float*)d_in[9];
    const float* Wp1    = (const float*)d_in[10];
    const float* bp1    = (const float*)d_in[11];
    const float* wp2    = (const float*)d_in[12];
    const float* bp2    = (const float*)d_in[13];
    float* out          = (float*)d_out;

    const int* esrc = ei;
    const int* edst = ei + EE;

    __half *hA, *hB, *hC, *hD, *uv, *Bf;
    float *s, *t;
    int *deg, *off, *cursor, *csrc;
    cudaGetSymbolAddress((void**)&hA, g_hA);
    cudaGetSymbolAddress((void**)&hB, g_hB);
    cudaGetSymbolAddress((void**)&hC, g_hC);
    cudaGetSymbolAddress((void**)&hD, g_hD);
    cudaGetSymbolAddress((void**)&uv, g_uv);
    cudaGetSymbolAddress((void**)&Bf, g_Bf);
    cudaGetSymbolAddress((void**)&s,  g_s);
    cudaGetSymbolAddress((void**)&t,  g_t);
    cudaGetSymbolAddress((void**)&deg, g_deg);
    cudaGetSymbolAddress((void**)&off, g_off);
    cudaGetSymbolAddress((void**)&cursor, g_cursor);
    cudaGetSymbolAddress((void**)&csrc, g_csrc);

    const int dynSmem = NSTG * STG_STAGE;   // 165888 bytes
    cudaFuncSetAttribute(mma_gemm_a32_kernel,
                         cudaFuncAttributeMaxDynamicSharedMemorySize, dynSmem);
    cudaFuncSetAttribute(mma_gemm_a16_kernel,
                         cudaFuncAttributeMaxDynamicSharedMemorySize, dynSmem);

    const int TPB = 256;
    dim3 gE((EE + TPB - 1) / TPB);
    const int GS_N = 888;
    const int GS_E = 1776;
    const int MB = (NN + GBM - 1) / GBM;   // 391

    cudaMemsetAsync(deg, 0, NN * sizeof(int));

    // launch order: GEMM1 is the 4th kernel launch (ncu profile slot)
    mega_pack_kernel<<<(BF_TOTAL + TPB - 1) / TPB, TPB>>>(W1, W2, Wp1, Bf);         // 1
    count_kernel<<<gE, TPB>>>(edst, deg, EE);                                       // 2
    scan_kernel<<<1, 1024>>>(deg, off, cursor, csrc, NN);                           // 3
    mma_gemm_a32_kernel<<<dim3(1, MB), 256, dynSmem>>>(x, Bf, hA, NN, 2048, 256,
                                                       a_src1, a_dst1, s, t);       // 4 (profiled)
    scatter_kernel<<<gE, TPB>>>(esrc, edst, cursor, csrc, EE);                      // 5

    gat_agg_kernel<<<GS_N, TPB>>>(hA, s, t, off, csrc, b1, hB, NN);                 // 6

    // ---- layer 2 (dots fused into epilogue) ----
    mma_gemm_a16_kernel<<<dim3(1, MB), 256, dynSmem>>>(hB, Bf + BF_W2_OFF, hC,
                                                       NN, 256, 256,
                                                       a_src2, a_dst2, s, t);       // 7
    gat_agg_kernel<<<GS_N, TPB>>>(hC, s, t, off, csrc, b2, hD, NN);                 // 8

    // ---- edge predictor: [u | v] = h2 @ [Wp1_top | Wp1_bot] (N=512) ----
    mma_gemm_a16_kernel<<<dim3(2, MB), 256, dynSmem>>>(hD, Bf + BF_WP_OFF, uv,
                                                       NN, 256, 512,
                                                       nullptr, nullptr,
                                                       nullptr, nullptr);           // 9
    edge_pred_kernel<<<GS_E, TPB>>>(uv, esrc, edst, bp1, wp2, bp2, out, EE);        // 10
}

// round 15
// speedup vs baseline: 1.0670x; 1.0670x over previous
#include <cuda_runtime.h>
#include <cuda_fp16.h>
#include <math.h>
#include <stdint.h>

#define NN 50000
#define EE 800000
#define DD 2048
#define CC 256
#define ESL (EE + NN)

// ---------------- scratch (static device globals; no runtime alloc) --------
__device__ __half g_hA[NN * CC];     // h1_pre (fp16)
__device__ __half g_hB[NN * CC];     // h1
__device__ __half g_hC[NN * CC];     // h2_pre
__device__ __half g_hD[NN * CC];     // h2
__device__ __half g_uv[NN * 512];    // [u | v] per node (fp16)
__device__ __half g_Bf[512 * 2048];  // packed weights: W1 | W2 | Wp1
__device__ float g_s[NN];
__device__ float g_t[NN];
__device__ int   g_deg[NN];
__device__ int   g_off[NN + 1];
__device__ int   g_cursor[NN];
__device__ int   g_csrc[ESL];
__device__ int   g_cedge[ESL];       // original edge id per CSR slot

#define BF_W1_OFF 0
#define BF_W2_OFF (256 * 2048)
#define BF_WP_OFF (256 * 2048 + 256 * 256)
#define BF_TOTAL  (256 * 2048 + 256 * 256 + 512 * 256)

// ================= helpers ==================================================
__device__ __forceinline__ uint32_t smem_u32(const void* p) {
    uint32_t a;
    asm("{ .reg .u64 t; cvta.to.shared.u64 t, %1; cvt.u32.u64 %0, t; }"
        : "=r"(a) : "l"(p));
    return a;
}

#define LDSM4(r, addr) \
    asm volatile("ldmatrix.sync.aligned.m8n8.x4.shared.b16 {%0,%1,%2,%3}, [%4];" \
        : "=r"((r)[0]), "=r"((r)[1]), "=r"((r)[2]), "=r"((r)[3]) : "r"(addr))

#define MMA16816(c, a, b0, b1) \
    asm volatile("mma.sync.aligned.m16n8k16.row.col.f32.f16.f16.f32 " \
        "{%0,%1,%2,%3}, {%4,%5,%6,%7}, {%8,%9}, {%0,%1,%2,%3};" \
        : "+f"((c)[0]), "+f"((c)[1]), "+f"((c)[2]), "+f"((c)[3]) \
        : "r"((a)[0]), "r"((a)[1]), "r"((a)[2]), "r"((a)[3]), "r"(b0), "r"(b1))

#define CP_ASYNC16(smem, gptr) \
    asm volatile("cp.async.cg.shared.global [%0], [%1], 16;" \
        :: "r"(smem), "l"(gptr) : "memory")
#define CP_COMMIT() asm volatile("cp.async.commit_group;" ::: "memory")
#define CP_WAIT1()  asm volatile("cp.async.wait_group 1;" ::: "memory")

// ---------------- CSR build -------------------------------------------------
__global__ void count_kernel(const int* __restrict__ dst, int* deg, int E) {
    int i = blockIdx.x * blockDim.x + threadIdx.x;
    if (i < E) atomicAdd(&deg[dst[i]], 1);
}

// tiled coalesced single-block exclusive scan; adds +1 per node (self loop)
// and fuses the selfloop placement (csrc[off]=i, cursor=off+1)
__global__ void scan_kernel(const int* __restrict__ deg, int* __restrict__ off,
                            int* __restrict__ cursor, int* __restrict__ csrc, int n) {
    __shared__ int warp_sums[32];
    const int tid  = threadIdx.x;
    const int lane = tid & 31;
    const int w    = tid >> 5;
    int carry = 0;
    for (int base = 0; base < n; base += 1024) {
        int i = base + tid;
        int v = (i < n) ? (deg[i] + 1) : 0;
        int x = v;
        #pragma unroll
        for (int o = 1; o < 32; o <<= 1) {
            int y = __shfl_up_sync(0xffffffffu, x, o);
            if (lane >= o) x += y;
        }
        if (lane == 31) warp_sums[w] = x;
        __syncthreads();
        if (w == 0) {
            int s = warp_sums[lane];
            #pragma unroll
            for (int o = 1; o < 32; o <<= 1) {
                int y = __shfl_up_sync(0xffffffffu, s, o);
                if (lane >= o) s += y;
            }
            warp_sums[lane] = s;
        }
        __syncthreads();
        int incl = x + (w > 0 ? warp_sums[w - 1] : 0);
        int total = warp_sums[31];
        if (i < n) {
            int o = carry + incl - v;
            off[i] = o;
            csrc[o] = i;           // self loop first (deterministic slot)
            cursor[i] = o + 1;
        }
        carry += total;
        __syncthreads();
    }
    if (tid == 0) off[n] = carry;
}

__global__ void scatter_kernel(const int* __restrict__ src, const int* __restrict__ dst,
                               int* cursor, int* csrc, int* cedge, int E) {
    int i = blockIdx.x * blockDim.x + threadIdx.x;
    if (i < E) {
        int d = dst[i];
        int p = atomicAdd(&cursor[d], 1);
        csrc[p] = src[i];
        cedge[p] = i;
    }
}

// ---------------- mega-pack: W1, W2, Wp1 -> g_Bf fp16 [N,K] -----------------
__global__ void mega_pack_kernel(const float* __restrict__ W1,
                                 const float* __restrict__ W2,
                                 const float* __restrict__ Wp1,
                                 __half* __restrict__ Bf) {
    int i = blockIdx.x * blockDim.x + threadIdx.x;
    if (i >= BF_TOTAL) return;
    if (i < BF_W2_OFF) {
        int n = i >> 11, k = i & 2047;
        Bf[i] = __float2half_rn(W1[(size_t)k * 256 + n]);
    } else if (i < BF_WP_OFF) {
        int j = i - BF_W2_OFF;
        int n = j >> 8, k = j & 255;
        Bf[i] = __float2half_rn(W2[(size_t)k * 256 + n]);
    } else {
        int j = i - BF_WP_OFF;
        int n = j >> 8, k = j & 255;
        int srcRow = (n < 256) ? k : (256 + k);
        int srcCol = (n < 256) ? n : (n - 256);
        Bf[i] = __float2half_rn(Wp1[(size_t)srcRow * 256 + srcCol]);
    }
}

// ---------------- mma.sync fp16 GEMM framework (BK=64) ----------------------
#define GBM 128
#define GBN 256
#define GBK 64
#define NSTG 3
#define LDAB 72
#define A_MAT (128 * LDAB * 2)         // 18432
#define B_MAT (256 * LDAB * 2)         // 36864
#define AH_OFF 0
#define BF_OFF A_MAT
#define STG_STAGE (A_MAT + B_MAT)      // 55296

#define EPILOGUE_FP16()                                                        \
    _Pragma("unroll")                                                          \
    for (int i = 0; i < 4; ++i) {                                              \
        int row0 = brow + wm + i * 16 + (lane >> 2);                           \
        _Pragma("unroll")                                                      \
        for (int j = 0; j < 8; ++j) {                                          \
            int col = bcol + wn + j * 8 + (lane & 3) * 2;                      \
            if (row0 < M) {                                                    \
                __half2 v = __floats2half2_rn(acc[i][j][0], acc[i][j][1]);     \
                *(__half2*)(C16 + (size_t)row0 * Nout + col) = v;              \
            }                                                                  \
            if (row0 + 8 < M) {                                                \
                __half2 v = __floats2half2_rn(acc[i][j][2], acc[i][j][3]);     \
                *(__half2*)(C16 + (size_t)(row0 + 8) * Nout + col) = v;        \
            }                                                                  \
        }                                                                      \
    }

#define GEMM_COMPUTE_BODY()                                                    \
    auto COMPUTE = [&](int t) {                                                \
        const uint32_t base = sb + (uint32_t)(t % NSTG) * STG_STAGE;           \
        _Pragma("unroll")                                                      \
        for (int ks = 0; ks < 4; ++ks) {                                       \
            const uint32_t coff = (uint32_t)(ks * 16 + lcol * 8) * 2;          \
            uint32_t bf[4][4], af[4][4];                                       \
            _Pragma("unroll")                                                  \
            for (int g = 0; g < 4; ++g) {                                      \
                uint32_t addr = base + (uint32_t)((wn + g * 16 + lrow) * LDAB) * 2 + coff; \
                LDSM4(bf[g], addr + BF_OFF);                                   \
            }                                                                  \
            _Pragma("unroll")                                                  \
            for (int i = 0; i < 4; ++i) {                                      \
                uint32_t aaddr = base + (uint32_t)((wm + i * 16 + lrow) * LDAB) * 2 + coff; \
                LDSM4(af[i], aaddr + AH_OFF);                                  \
            }                                                                  \
            _Pragma("unroll")                                                  \
            for (int i = 0; i < 4; ++i)                                        \
                _Pragma("unroll")                                              \
                for (int j = 0; j < 8; ++j) {                                  \
                    int g = j >> 1, sel = j & 1;                               \
                    MMA16816(acc[i][j], af[i], bf[g][sel], bf[g][sel + 2]);    \
                }                                                              \
        }                                                                      \
    };

// --- variant 1: A fp32 (converted in-kernel), used for GEMM1 only -----------
__global__ void __launch_bounds__(256, 1)
mma_gemm_a32_kernel(const float* __restrict__ A,
                    const __half* __restrict__ Bfp,
                    __half* __restrict__ C16, int M, int Ktot, int Nout)
{
    extern __shared__ char sm[];
    const uint32_t sb = smem_u32(sm);

    const int tid  = threadIdx.x;
    const int wid  = tid >> 5;
    const int lane = tid & 31;
    const int brow = blockIdx.y * GBM;
    const int bcol = blockIdx.x * GBN;
    const int wm   = (wid & 1) * 64;
    const int wn   = (wid >> 1) * 64;

    float acc[4][8][4];
    #pragma unroll
    for (int i = 0; i < 4; i++)
        #pragma unroll
        for (int j = 0; j < 8; j++)
            #pragma unroll
            for (int r = 0; r < 4; r++) acc[i][j][r] = 0.f;

    const int T = Ktot / GBK;

    auto ISSUE_B = [&](int t) {
        const int kt = t * GBK;
        const uint32_t stage = sb + (uint32_t)(t % NSTG) * STG_STAGE;
        #pragma unroll
        for (int it = 0; it < 8; ++it) {
            int idx = tid + it * 256;
            int rr  = idx >> 3;
            int cc  = idx & 7;
            uint64_t g = __cvta_generic_to_global(
                Bfp + (size_t)(bcol + rr) * Ktot + kt + cc * 8);
            uint32_t sa = stage + (uint32_t)BF_OFF
                        + (uint32_t)rr * (LDAB * 2) + (uint32_t)cc * 16;
            CP_ASYNC16(sa, g);
        }
        CP_COMMIT();
    };

    float4 pa[8];
    auto LOAD_A = [&](int t) {
        const int kt = t * GBK;
        #pragma unroll
        for (int it = 0; it < 8; ++it) {
            int idx = tid + it * 256;
            int r = idx >> 4, c4 = (idx & 15) * 4;
            pa[it] = (brow + r < M)
                ? *(const float4*)(A + (size_t)(brow + r) * Ktot + kt + c4)
                : make_float4(0.f, 0.f, 0.f, 0.f);
        }
    };

    auto STORE_A = [&](int t) {
        char* st = sm + (t % NSTG) * STG_STAGE;
        #pragma unroll
        for (int it = 0; it < 8; ++it) {
            int idx = tid + it * 256;
            int r = idx >> 4, c4 = (idx & 15) * 4;
            float4 v = pa[it];
            __half2 h01 = __floats2half2_rn(v.x, v.y);
            __half2 h23 = __floats2half2_rn(v.z, v.w);
            uint2 hp;
            hp.x = *(uint32_t*)&h01;
            hp.y = *(uint32_t*)&h23;
            uint32_t off = (uint32_t)(r * LDAB + c4) * 2;
            *(uint2*)(st + AH_OFF + off) = hp;
        }
    };

    const int lrow = lane & 15;
    const int lcol = (lane >> 4) & 1;

    GEMM_COMPUTE_BODY()

    ISSUE_B(0);
    ISSUE_B(1);
    LOAD_A(0);
    STORE_A(0);
    LOAD_A(1);

    for (int t = 0; t < T; ++t) {
        CP_WAIT1();
        __syncthreads();
        if (t + 1 < T) STORE_A(t + 1);
        if (t + 2 < T) { ISSUE_B(t + 2); LOAD_A(t + 2); }
        COMPUTE(t);
    }

    EPILOGUE_FP16()
}

// --- variant 2: A fp16 via cp.async (GEMM2, uv GEMM) ------------------------
__global__ void __launch_bounds__(256, 1)
mma_gemm_a16_kernel(const __half* __restrict__ A16,
                    const __half* __restrict__ Bfp,
                    __half* __restrict__ C16, int M, int Ktot, int Nout)
{
    extern __shared__ char sm[];
    const uint32_t sb = smem_u32(sm);

    const int tid  = threadIdx.x;
    const int wid  = tid >> 5;
    const int lane = tid & 31;
    const int brow = blockIdx.y * GBM;
    const int bcol = blockIdx.x * GBN;
    const int wm   = (wid & 1) * 64;
    const int wn   = (wid >> 1) * 64;

    float acc[4][8][4];
    #pragma unroll
    for (int i = 0; i < 4; i++)
        #pragma unroll
        for (int j = 0; j < 8; j++)
            #pragma unroll
            for (int r = 0; r < 4; r++) acc[i][j][r] = 0.f;

    const int T = Ktot / GBK;

    auto ISSUE_AB = [&](int t) {
        const int kt = t * GBK;
        const uint32_t stage = sb + (uint32_t)(t % NSTG) * STG_STAGE;
        #pragma unroll
        for (int it = 0; it < 4; ++it) {
            int idx = tid + it * 256;
            int rr = idx >> 3;
            int cc = idx & 7;
            int row = brow + rr; if (row >= M) row = M - 1;
            uint64_t g = __cvta_generic_to_global(
                A16 + (size_t)row * Ktot + kt + cc * 8);
            uint32_t sa = stage + (uint32_t)AH_OFF
                        + (uint32_t)rr * (LDAB * 2) + (uint32_t)cc * 16;
            CP_ASYNC16(sa, g);
        }
        #pragma unroll
        for (int it = 0; it < 8; ++it) {
            int idx = tid + it * 256;
            int rr  = idx >> 3;
            int cc  = idx & 7;
            uint64_t g = __cvta_generic_to_global(
                Bfp + (size_t)(bcol + rr) * Ktot + kt + cc * 8);
            uint32_t sa = stage + (uint32_t)BF_OFF
                        + (uint32_t)rr * (LDAB * 2) + (uint32_t)cc * 16;
            CP_ASYNC16(sa, g);
        }
        CP_COMMIT();
    };

    const int lrow = lane & 15;
    const int lcol = (lane >> 4) & 1;

    GEMM_COMPUTE_BODY()

    ISSUE_AB(0);
    ISSUE_AB(1);

    for (int t = 0; t < T; ++t) {
        CP_WAIT1();
        __syncthreads();
        if (t + 2 < T) ISSUE_AB(t + 2);
        COMPUTE(t);
    }

    EPILOGUE_FP16()
}

// ---------------- per-node attention scalars (grid-stride warps) ------------
__global__ void node_dots_kernel(const __half* __restrict__ h,
                                 const float* __restrict__ a_src,
                                 const float* __restrict__ a_dst,
                                 float* __restrict__ s, float* __restrict__ t, int n)
{
    int gw   = (blockIdx.x * blockDim.x + threadIdx.x) >> 5;
    int nwp  = (gridDim.x * blockDim.x) >> 5;
    int lane = threadIdx.x & 31;
    float4 a0 = *(const float4*)(a_src + lane * 8);
    float4 a1 = *(const float4*)(a_src + lane * 8 + 4);
    float4 d0 = *(const float4*)(a_dst + lane * 8);
    float4 d1 = *(const float4*)(a_dst + lane * 8 + 4);
    for (int node = gw; node < n; node += nwp) {
        uint4 hv = *(const uint4*)(h + (size_t)node * CC + lane * 8);
        const __half2* hh = (const __half2*)&hv;
        float2 f0 = __half22float2(hh[0]);
        float2 f1 = __half22float2(hh[1]);
        float2 f2 = __half22float2(hh[2]);
        float2 f3 = __half22float2(hh[3]);
        float ss = f0.x * a0.x + f0.y * a0.y + f1.x * a0.z + f1.y * a0.w
                 + f2.x * a1.x + f2.y * a1.y + f3.x * a1.z + f3.y * a1.w;
        float tt = f0.x * d0.x + f0.y * d0.y + f1.x * d0.z + f1.y * d0.w
                 + f2.x * d1.x + f2.y * d1.y + f3.x * d1.z + f3.y * d1.w;
        #pragma unroll
        for (int o = 16; o > 0; o >>= 1) {
            ss += __shfl_down_sync(0xffffffffu, ss, o);
            tt += __shfl_down_sync(0xffffffffu, tt, o);
        }
        if (lane == 0) { s[node] = ss; t[node] = tt; }
    }
}

// ---------------- single-pass softmax aggregation (grid-stride warps) -------
__global__ void gat_agg_kernel(const __half* __restrict__ h,
                               const float* __restrict__ s,
                               const float* __restrict__ t,
                               const int* __restrict__ off,
                               const int* __restrict__ csrc,
                               const float* __restrict__ bias,
                               __half* __restrict__ out, int n)
{
    int gw   = (blockIdx.x * blockDim.x + threadIdx.x) >> 5;
    int nwp  = (gridDim.x * blockDim.x) >> 5;
    int lane = threadIdx.x & 31;
    float4 b0 = *(const float4*)(bias + lane * 8);
    float4 b1 = *(const float4*)(bias + lane * 8 + 4);

    for (int node = gw; node < n; node += nwp) {
        int beg = off[node], end = off[node + 1];
        float tv = t[node];
        float d = 0.f;
        float acc[8];
        #pragma unroll
        for (int q = 0; q < 8; q++) acc[q] = 0.f;

        for (int p = beg; p < end; ++p) {
            int src = csrc[p];
            float e = s[src] + tv;
            e = (e > 0.f) ? e : 0.2f * e;
            float w = __expf(e);
            d += w;
            uint4 hv = *(const uint4*)(h + (size_t)src * CC + lane * 8);
            const __half2* hh = (const __half2*)&hv;
            #pragma unroll
            for (int q = 0; q < 4; q++) {
                float2 f = __half22float2(hh[q]);
                acc[2 * q]     += w * f.x;
                acc[2 * q + 1] += w * f.y;
            }
        }

        float inv = 1.f / (d + 1e-16f);
        __half2 o_[4];
        o_[0] = __floats2half2_rn(acc[0] * inv + b0.x, acc[1] * inv + b0.y);
        o_[1] = __floats2half2_rn(acc[2] * inv + b0.z, acc[3] * inv + b0.w);
        o_[2] = __floats2half2_rn(acc[4] * inv + b1.x, acc[5] * inv + b1.y);
        o_[3] = __floats2half2_rn(acc[6] * inv + b1.z, acc[7] * inv + b1.w);
        *(uint4*)(out + (size_t)node * CC + lane * 8) = *(uint4*)o_;
    }
}

// ---------------- edge predictor over CSR (v-row reuse per dst node) --------
__global__ void edge_pred_csr_kernel(const __half* __restrict__ uv,
                                     const int* __restrict__ off,
                                     const int* __restrict__ csrc,
                                     const int* __restrict__ cedge,
                                     const float* __restrict__ bp1,
                                     const float* __restrict__ wp2,
                                     const float* __restrict__ bp2,
                                     float* __restrict__ out, int n)
{
    int gw   = (blockIdx.x * blockDim.x + threadIdx.x) >> 5;
    int nwp  = (gridDim.x * blockDim.x) >> 5;
    int lane = threadIdx.x & 31;
    float4 b0 = *(const float4*)(bp1 + lane * 8);
    float4 b1 = *(const float4*)(bp1 + lane * 8 + 4);
    float4 w0 = *(const float4*)(wp2 + lane * 8);
    float4 w1 = *(const float4*)(wp2 + lane * 8 + 4);
    float bb[8] = {b0.x, b0.y, b0.z, b0.w, b1.x, b1.y, b1.z, b1.w};
    float ww[8] = {w0.x, w0.y, w0.z, w0.w, w1.x, w1.y, w1.z, w1.w};
    float bias2 = bp2[0];

    for (int node = gw; node < n; node += nwp) {
        int beg = off[node] + 1;          // skip self-loop slot
        int end = off[node + 1];
        if (beg >= end) continue;
        // load v[node] once, fold in bias: fvb[q] = v_q + b_q
        uint4 vv = *(const uint4*)(uv + (size_t)node * 512 + 256 + lane * 8);
        const __half2* v2 = (const __half2*)&vv;
        float fvb[8];
        #pragma unroll
        for (int q = 0; q < 4; q++) {
            float2 f = __half22float2(v2[q]);
            fvb[2 * q]     = f.x + bb[2 * q];
            fvb[2 * q + 1] = f.y + bb[2 * q + 1];
        }
        for (int p = beg; p < end; ++p) {
            int src = csrc[p];            // broadcast
            int eid = cedge[p];           // broadcast
            uint4 uu = *(const uint4*)(uv + (size_t)src * 512 + lane * 8);
            const __half2* u2 = (const __half2*)&uu;
            float sum = 0.f;
            #pragma unroll
            for (int q = 0; q < 4; q++) {
                float2 fu = __half22float2(u2[q]);
                float r0 = fmaxf(fu.x + fvb[2 * q], 0.f);
                float r1 = fmaxf(fu.y + fvb[2 * q + 1], 0.f);
                sum += r0 * ww[2 * q] + r1 * ww[2 * q + 1];
            }
            #pragma unroll
            for (int o = 16; o > 0; o >>= 1)
                sum += __shfl_down_sync(0xffffffffu, sum, o);
            if (lane == 0) out[eid] = sum + bias2;
        }
    }
}

// ---------------- host driver -----------------------------------------------
extern "C" void kernel_launch(void* const* d_in, const int* in_sizes, int n_in,
                              void* d_out, int out_size)
{
    const float* x      = (const float*)d_in[0];
    const int*   ei     = (const int*)  d_in[1];
    const float* W1     = (const float*)d_in[2];
    const float* a_src1 = (const float*)d_in[3];
    const float* a_dst1 = (const float*)d_in[4];
    const float* b1     = (const float*)d_in[5];
    const float* W2     = (const float*)d_in[6];
    const float* a_src2 = (const float*)d_in[7];
    const float* a_dst2 = (const float*)d_in[8];
    const float* b2     = (const float*)d_in[9];
    const float* Wp1    = (const float*)d_in[10];
    const float* bp1    = (const float*)d_in[11];
    const float* wp2    = (const float*)d_in[12];
    const float* bp2    = (const float*)d_in[13];
    float* out          = (float*)d_out;

    const int* esrc = ei;
    const int* edst = ei + EE;

    __half *hA, *hB, *hC, *hD, *uv, *Bf;
    float *s, *t;
    int *deg, *off, *cursor, *csrc, *cedge;
    cudaGetSymbolAddress((void**)&hA, g_hA);
    cudaGetSymbolAddress((void**)&hB, g_hB);
    cudaGetSymbolAddress((void**)&hC, g_hC);
    cudaGetSymbolAddress((void**)&hD, g_hD);
    cudaGetSymbolAddress((void**)&uv, g_uv);
    cudaGetSymbolAddress((void**)&Bf, g_Bf);
    cudaGetSymbolAddress((void**)&s,  g_s);
    cudaGetSymbolAddress((void**)&t,  g_t);
    cudaGetSymbolAddress((void**)&deg, g_deg);
    cudaGetSymbolAddress((void**)&off, g_off);
    cudaGetSymbolAddress((void**)&cursor, g_cursor);
    cudaGetSymbolAddress((void**)&csrc, g_csrc);
    cudaGetSymbolAddress((void**)&cedge, g_cedge);

    const int dynSmem = NSTG * STG_STAGE;   // 165888 bytes
    cudaFuncSetAttribute(mma_gemm_a32_kernel,
                         cudaFuncAttributeMaxDynamicSharedMemorySize, dynSmem);
    cudaFuncSetAttribute(mma_gemm_a16_kernel,
                         cudaFuncAttributeMaxDynamicSharedMemorySize, dynSmem);

    const int TPB = 256;
    dim3 gE((EE + TPB - 1) / TPB);
    const int GS_N = 888;
    const int MB = (NN + GBM - 1) / GBM;   // 391

    cudaMemsetAsync(deg, 0, NN * sizeof(int));

    // launch order: GEMM1 is the 4th kernel launch (ncu profile slot)
    mega_pack_kernel<<<(BF_TOTAL + TPB - 1) / TPB, TPB>>>(W1, W2, Wp1, Bf);         // 1
    count_kernel<<<gE, TPB>>>(edst, deg, EE);                                       // 2
    scan_kernel<<<1, 1024>>>(deg, off, cursor, csrc, NN);                           // 3
    mma_gemm_a32_kernel<<<dim3(1, MB), 256, dynSmem>>>(x, Bf, hA, NN, 2048, 256);   // 4 (profiled)
    scatter_kernel<<<gE, TPB>>>(esrc, edst, cursor, csrc, cedge, EE);               // 5

    node_dots_kernel<<<GS_N, TPB>>>(hA, a_src1, a_dst1, s, t, NN);                  // 6
    gat_agg_kernel<<<GS_N, TPB>>>(hA, s, t, off, csrc, b1, hB, NN);                 // 7

    // ---- layer 2 ----
    mma_gemm_a16_kernel<<<dim3(1, MB), 256, dynSmem>>>(hB, Bf + BF_W2_OFF, hC,
                                                       NN, 256, 256);               // 8
    node_dots_kernel<<<GS_N, TPB>>>(hC, a_src2, a_dst2, s, t, NN);                  // 9
    gat_agg_kernel<<<GS_N, TPB>>>(hC, s, t, off, csrc, b2, hD, NN);                 // 10

    // ---- edge predictor: [u | v] = h2 @ [Wp1_top | Wp1_bot] (N=512) ----
    mma_gemm_a16_kernel<<<dim3(2, MB), 256, dynSmem>>>(hD, Bf + BF_WP_OFF, uv,
                                                       NN, 256, 512);               // 11
    edge_pred_csr_kernel<<<GS_N, TPB>>>(uv, off, csrc, cedge, bp1, wp2, bp2,
                                        out, NN);                                   // 12
}

// round 16
// speedup vs baseline: 1.0689x; 1.0018x over previous
#include <cuda_runtime.h>
#include <cuda_fp16.h>
#include <math.h>
#include <stdint.h>

#define NN 50000
#define EE 800000
#define DD 2048
#define CC 256
#define ESL (EE + NN)

// ---------------- scratch (static device globals; no runtime alloc) --------
__device__ __half g_hA[NN * CC];     // h1_pre (fp16)
__device__ __half g_hB[NN * CC];     // h1
__device__ __half g_hC[NN * CC];     // h2_pre
__device__ __half g_hD[NN * CC];     // h2
__device__ __half g_uv[NN * 512];    // [u | v] per node (fp16)
__device__ __half g_Bf[512 * 2048];  // packed weights: W1 | W2 | Wp1
__device__ float g_s[NN];
__device__ float g_t[NN];
__device__ int   g_deg[NN];
__device__ int   g_off[NN + 1];
__device__ int   g_cursor[NN];
__device__ int   g_csrc[ESL];
__device__ int   g_cedge[ESL];       // original edge id per CSR slot

#define BF_W1_OFF 0
#define BF_W2_OFF (256 * 2048)
#define BF_WP_OFF (256 * 2048 + 256 * 256)
#define BF_TOTAL  (256 * 2048 + 256 * 256 + 512 * 256)

// ================= helpers ==================================================
__device__ __forceinline__ uint32_t smem_u32(const void* p) {
    uint32_t a;
    asm("{ .reg .u64 t; cvta.to.shared.u64 t, %1; cvt.u32.u64 %0, t; }"
        : "=r"(a) : "l"(p));
    return a;
}

#define LDSM4(r, addr) \
    asm volatile("ldmatrix.sync.aligned.m8n8.x4.shared.b16 {%0,%1,%2,%3}, [%4];" \
        : "=r"((r)[0]), "=r"((r)[1]), "=r"((r)[2]), "=r"((r)[3]) : "r"(addr))

#define MMA16816(c, a, b0, b1) \
    asm volatile("mma.sync.aligned.m16n8k16.row.col.f32.f16.f16.f32 " \
        "{%0,%1,%2,%3}, {%4,%5,%6,%7}, {%8,%9}, {%0,%1,%2,%3};" \
        : "+f"((c)[0]), "+f"((c)[1]), "+f"((c)[2]), "+f"((c)[3]) \
        : "r"((a)[0]), "r"((a)[1]), "r"((a)[2]), "r"((a)[3]), "r"(b0), "r"(b1))

#define CP_ASYNC16(smem, gptr) \
    asm volatile("cp.async.cg.shared.global [%0], [%1], 16;" \
        :: "r"(smem), "l"(gptr) : "memory")
#define CP_COMMIT() asm volatile("cp.async.commit_group;" ::: "memory")
#define CP_WAIT1()  asm volatile("cp.async.wait_group 1;" ::: "memory")

// ---------------- fused: mega-pack + degree count ---------------------------
#define PACK_BLOCKS ((BF_TOTAL + 255) / 256)
#define COUNT_BLOCKS ((EE + 255) / 256)

__global__ void pack_count_kernel(const float* __restrict__ W1,
                                  const float* __restrict__ W2,
                                  const float* __restrict__ Wp1,
                                  __half* __restrict__ Bf,
                                  const int* __restrict__ dst, int* deg) {
    int b = blockIdx.x;
    if (b < PACK_BLOCKS) {
        int i = b * 256 + threadIdx.x;
        if (i >= BF_TOTAL) return;
        if (i < BF_W2_OFF) {
            int n = i >> 11, k = i & 2047;
            Bf[i] = __float2half_rn(W1[(size_t)k * 256 + n]);
        } else if (i < BF_WP_OFF) {
            int j = i - BF_W2_OFF;
            int n = j >> 8, k = j & 255;
            Bf[i] = __float2half_rn(W2[(size_t)k * 256 + n]);
        } else {
            int j = i - BF_WP_OFF;
            int n = j >> 8, k = j & 255;
            int srcRow = (n < 256) ? k : (256 + k);
            int srcCol = (n < 256) ? n : (n - 256);
            Bf[i] = __float2half_rn(Wp1[(size_t)srcRow * 256 + srcCol]);
        }
    } else {
        int i = (b - PACK_BLOCKS) * 256 + threadIdx.x;
        if (i < EE) atomicAdd(&deg[dst[i]], 1);
    }
}

// tiled coalesced single-block exclusive scan; adds +1 per node (self loop)
// and fuses the selfloop placement (csrc[off]=i, cursor=off+1)
__global__ void scan_kernel(const int* __restrict__ deg, int* __restrict__ off,
                            int* __restrict__ cursor, int* __restrict__ csrc, int n) {
    __shared__ int warp_sums[32];
    const int tid  = threadIdx.x;
    const int lane = tid & 31;
    const int w    = tid >> 5;
    int carry = 0;
    for (int base = 0; base < n; base += 1024) {
        int i = base + tid;
        int v = (i < n) ? (deg[i] + 1) : 0;
        int x = v;
        #pragma unroll
        for (int o = 1; o < 32; o <<= 1) {
            int y = __shfl_up_sync(0xffffffffu, x, o);
            if (lane >= o) x += y;
        }
        if (lane == 31) warp_sums[w] = x;
        __syncthreads();
        if (w == 0) {
            int s = warp_sums[lane];
            #pragma unroll
            for (int o = 1; o < 32; o <<= 1) {
                int y = __shfl_up_sync(0xffffffffu, s, o);
                if (lane >= o) s += y;
            }
            warp_sums[lane] = s;
        }
        __syncthreads();
        int incl = x + (w > 0 ? warp_sums[w - 1] : 0);
        int total = warp_sums[31];
        if (i < n) {
            int o = carry + incl - v;
            off[i] = o;
            csrc[o] = i;
            cursor[i] = o + 1;
        }
        carry += total;
        __syncthreads();
    }
    if (tid == 0) off[n] = carry;
}

// ---------------- fused: scatter + node_dots(layer1) ------------------------
#define SCAT_BLOCKS ((EE + 255) / 256)
#define DOTS_BLOCKS 888

__global__ void scatter_dots_kernel(const int* __restrict__ src,
                                    const int* __restrict__ dst,
                                    int* cursor, int* csrc, int* cedge,
                                    const __half* __restrict__ h,
                                    const float* __restrict__ a_src,
                                    const float* __restrict__ a_dst,
                                    float* __restrict__ s, float* __restrict__ t) {
    int b = blockIdx.x;
    if (b < SCAT_BLOCKS) {
        int i = b * 256 + threadIdx.x;
        if (i < EE) {
            int d = dst[i];
            int p = atomicAdd(&cursor[d], 1);
            csrc[p] = src[i];
            cedge[p] = i;
        }
    } else {
        int gw   = ((b - SCAT_BLOCKS) * 256 + threadIdx.x) >> 5;
        int nwp  = (DOTS_BLOCKS * 256) >> 5;
        int lane = threadIdx.x & 31;
        float4 a0 = *(const float4*)(a_src + lane * 8);
        float4 a1 = *(const float4*)(a_src + lane * 8 + 4);
        float4 d0 = *(const float4*)(a_dst + lane * 8);
        float4 d1 = *(const float4*)(a_dst + lane * 8 + 4);
        for (int node = gw; node < NN; node += nwp) {
            uint4 hv = *(const uint4*)(h + (size_t)node * CC + lane * 8);
            const __half2* hh = (const __half2*)&hv;
            float2 f0 = __half22float2(hh[0]);
            float2 f1 = __half22float2(hh[1]);
            float2 f2 = __half22float2(hh[2]);
            float2 f3 = __half22float2(hh[3]);
            float ss = f0.x * a0.x + f0.y * a0.y + f1.x * a0.z + f1.y * a0.w
                     + f2.x * a1.x + f2.y * a1.y + f3.x * a1.z + f3.y * a1.w;
            float tt = f0.x * d0.x + f0.y * d0.y + f1.x * d0.z + f1.y * d0.w
                     + f2.x * d1.x + f2.y * d1.y + f3.x * d1.z + f3.y * d1.w;
            #pragma unroll
            for (int o = 16; o > 0; o >>= 1) {
                ss += __shfl_down_sync(0xffffffffu, ss, o);
                tt += __shfl_down_sync(0xffffffffu, tt, o);
            }
            if (lane == 0) { s[node] = ss; t[node] = tt; }
        }
    }
}

// ---------------- mma.sync fp16 GEMM framework (BK=64) ----------------------
#define GBM 128
#define GBN 256
#define GBK 64
#define NSTG 3
#define LDAB 72
#define A_MAT (128 * LDAB * 2)
#define B_MAT (256 * LDAB * 2)
#define AH_OFF 0
#define BF_OFF A_MAT
#define STG_STAGE (A_MAT + B_MAT)

#define EPILOGUE_FP16()                                                        \
    _Pragma("unroll")                                                          \
    for (int i = 0; i < 4; ++i) {                                              \
        int row0 = brow + wm + i * 16 + (lane >> 2);                           \
        _Pragma("unroll")                                                      \
        for (int j = 0; j < 8; ++j) {                                          \
            int col = bcol + wn + j * 8 + (lane & 3) * 2;                      \
            if (row0 < M) {                                                    \
                __half2 v = __floats2half2_rn(acc[i][j][0], acc[i][j][1]);     \
                *(__half2*)(C16 + (size_t)row0 * Nout + col) = v;              \
            }                                                                  \
            if (row0 + 8 < M) {                                                \
                __half2 v = __floats2half2_rn(acc[i][j][2], acc[i][j][3]);     \
                *(__half2*)(C16 + (size_t)(row0 + 8) * Nout + col) = v;        \
            }                                                                  \
        }                                                                      \
    }

#define GEMM_COMPUTE_BODY()                                                    \
    auto COMPUTE = [&](int t) {                                                \
        const uint32_t base = sb + (uint32_t)(t % NSTG) * STG_STAGE;           \
        _Pragma("unroll")                                                      \
        for (int ks = 0; ks < 4; ++ks) {                                       \
            const uint32_t coff = (uint32_t)(ks * 16 + lcol * 8) * 2;          \
            uint32_t bf[4][4], af[4][4];                                       \
            _Pragma("unroll")                                                  \
            for (int g = 0; g < 4; ++g) {                                      \
                uint32_t addr = base + (uint32_t)((wn + g * 16 + lrow) * LDAB) * 2 + coff; \
                LDSM4(bf[g], addr + BF_OFF);                                   \
            }                                                                  \
            _Pragma("unroll")                                                  \
            for (int i = 0; i < 4; ++i) {                                      \
                uint32_t aaddr = base + (uint32_t)((wm + i * 16 + lrow) * LDAB) * 2 + coff; \
                LDSM4(af[i], aaddr + AH_OFF);                                  \
            }                                                                  \
            _Pragma("unroll")                                                  \
            for (int i = 0; i < 4; ++i)                                        \
                _Pragma("unroll")                                              \
                for (int j = 0; j < 8; ++j) {                                  \
                    int g = j >> 1, sel = j & 1;                               \
                    MMA16816(acc[i][j], af[i], bf[g][sel], bf[g][sel + 2]);    \
                }                                                              \
        }                                                                      \
    };

// --- variant 1: A fp32 (converted in-kernel), used for GEMM1 only -----------
__global__ void __launch_bounds__(256, 1)
mma_gemm_a32_kernel(const float* __restrict__ A,
                    const __half* __restrict__ Bfp,
                    __half* __restrict__ C16, int M, int Ktot, int Nout)
{
    extern __shared__ char sm[];
    const uint32_t sb = smem_u32(sm);

    const int tid  = threadIdx.x;
    const int wid  = tid >> 5;
    const int lane = tid & 31;
    const int brow = blockIdx.y * GBM;
    const int bcol = blockIdx.x * GBN;
    const int wm   = (wid & 1) * 64;
    const int wn   = (wid >> 1) * 64;

    float acc[4][8][4];
    #pragma unroll
    for (int i = 0; i < 4; i++)
        #pragma unroll
        for (int j = 0; j < 8; j++)
            #pragma unroll
            for (int r = 0; r < 4; r++) acc[i][j][r] = 0.f;

    const int T = Ktot / GBK;

    auto ISSUE_B = [&](int t) {
        const int kt = t * GBK;
        const uint32_t stage = sb + (uint32_t)(t % NSTG) * STG_STAGE;
        #pragma unroll
        for (int it = 0; it < 8; ++it) {
            int idx = tid + it * 256;
            int rr  = idx >> 3;
            int cc  = idx & 7;
            uint64_t g = __cvta_generic_to_global(
                Bfp + (size_t)(bcol + rr) * Ktot + kt + cc * 8);
            uint32_t sa = stage + (uint32_t)BF_OFF
                        + (uint32_t)rr * (LDAB * 2) + (uint32_t)cc * 16;
            CP_ASYNC16(sa, g);
        }
        CP_COMMIT();
    };

    float4 pa[8];
    auto LOAD_A = [&](int t) {
        const int kt = t * GBK;
        #pragma unroll
        for (int it = 0; it < 8; ++it) {
            int idx = tid + it * 256;
            int r = idx >> 4, c4 = (idx & 15) * 4;
            pa[it] = (brow + r < M)
                ? *(const float4*)(A + (size_t)(brow + r) * Ktot + kt + c4)
                : make_float4(0.f, 0.f, 0.f, 0.f);
        }
    };

    auto STORE_A = [&](int t) {
        char* st = sm + (t % NSTG) * STG_STAGE;
        #pragma unroll
        for (int it = 0; it < 8; ++it) {
            int idx = tid + it * 256;
            int r = idx >> 4, c4 = (idx & 15) * 4;
            float4 v = pa[it];
            __half2 h01 = __floats2half2_rn(v.x, v.y);
            __half2 h23 = __floats2half2_rn(v.z, v.w);
            uint2 hp;
            hp.x = *(uint32_t*)&h01;
            hp.y = *(uint32_t*)&h23;
            uint32_t off = (uint32_t)(r * LDAB + c4) * 2;
            *(uint2*)(st + AH_OFF + off) = hp;
        }
    };

    const int lrow = lane & 15;
    const int lcol = (lane >> 4) & 1;

    GEMM_COMPUTE_BODY()

    ISSUE_B(0);
    ISSUE_B(1);
    LOAD_A(0);
    STORE_A(0);
    LOAD_A(1);

    for (int t = 0; t < T; ++t) {
        CP_WAIT1();
        __syncthreads();
        if (t + 1 < T) STORE_A(t + 1);
        if (t + 2 < T) { ISSUE_B(t + 2); LOAD_A(t + 2); }
        COMPUTE(t);
    }

    EPILOGUE_FP16()
}

// --- variant 2: A fp16 via cp.async (GEMM2, uv GEMM) ------------------------
__global__ void __launch_bounds__(256, 1)
mma_gemm_a16_kernel(const __half* __restrict__ A16,
                    const __half* __restrict__ Bfp,
                    __half* __restrict__ C16, int M, int Ktot, int Nout)
{
    extern __shared__ char sm[];
    const uint32_t sb = smem_u32(sm);

    const int tid  = threadIdx.x;
    const int wid  = tid >> 5;
    const int lane = tid & 31;
    const int brow = blockIdx.y * GBM;
    const int bcol = blockIdx.x * GBN;
    const int wm   = (wid & 1) * 64;
    const int wn   = (wid >> 1) * 64;

    float acc[4][8][4];
    #pragma unroll
    for (int i = 0; i < 4; i++)
        #pragma unroll
        for (int j = 0; j < 8; j++)
            #pragma unroll
            for (int r = 0; r < 4; r++) acc[i][j][r] = 0.f;

    const int T = Ktot / GBK;

    auto ISSUE_AB = [&](int t) {
        const int kt = t * GBK;
        const uint32_t stage = sb + (uint32_t)(t % NSTG) * STG_STAGE;
        #pragma unroll
        for (int it = 0; it < 4; ++it) {
            int idx = tid + it * 256;
            int rr = idx >> 3;
            int cc = idx & 7;
            int row = brow + rr; if (row >= M) row = M - 1;
            uint64_t g = __cvta_generic_to_global(
                A16 + (size_t)row * Ktot + kt + cc * 8);
            uint32_t sa = stage + (uint32_t)AH_OFF
                        + (uint32_t)rr * (LDAB * 2) + (uint32_t)cc * 16;
            CP_ASYNC16(sa, g);
        }
        #pragma unroll
        for (int it = 0; it < 8; ++it) {
            int idx = tid + it * 256;
            int rr  = idx >> 3;
            int cc  = idx & 7;
            uint64_t g = __cvta_generic_to_global(
                Bfp + (size_t)(bcol + rr) * Ktot + kt + cc * 8);
            uint32_t sa = stage + (uint32_t)BF_OFF
                        + (uint32_t)rr * (LDAB * 2) + (uint32_t)cc * 16;
            CP_ASYNC16(sa, g);
        }
        CP_COMMIT();
    };

    const int lrow = lane & 15;
    const int lcol = (lane >> 4) & 1;

    GEMM_COMPUTE_BODY()

    ISSUE_AB(0);
    ISSUE_AB(1);

    for (int t = 0; t < T; ++t) {
        CP_WAIT1();
        __syncthreads();
        if (t + 2 < T) ISSUE_AB(t + 2);
        COMPUTE(t);
    }

    EPILOGUE_FP16()
}

// ---------------- per-node attention scalars (grid-stride warps) ------------
__global__ void node_dots_kernel(const __half* __restrict__ h,
                                 const float* __restrict__ a_src,
                                 const float* __restrict__ a_dst,
                                 float* __restrict__ s, float* __restrict__ t, int n)
{
    int gw   = (blockIdx.x * blockDim.x + threadIdx.x) >> 5;
    int nwp  = (gridDim.x * blockDim.x) >> 5;
    int lane = threadIdx.x & 31;
    float4 a0 = *(const float4*)(a_src + lane * 8);
    float4 a1 = *(const float4*)(a_src + lane * 8 + 4);
    float4 d0 = *(const float4*)(a_dst + lane * 8);
    float4 d1 = *(const float4*)(a_dst + lane * 8 + 4);
    for (int node = gw; node < n; node += nwp) {
        uint4 hv = *(const uint4*)(h + (size_t)node * CC + lane * 8);
        const __half2* hh = (const __half2*)&hv;
        float2 f0 = __half22float2(hh[0]);
        float2 f1 = __half22float2(hh[1]);
        float2 f2 = __half22float2(hh[2]);
        float2 f3 = __half22float2(hh[3]);
        float ss = f0.x * a0.x + f0.y * a0.y + f1.x * a0.z + f1.y * a0.w
                 + f2.x * a1.x + f2.y * a1.y + f3.x * a1.z + f3.y * a1.w;
        float tt = f0.x * d0.x + f0.y * d0.y + f1.x * d0.z + f1.y * d0.w
                 + f2.x * d1.x + f2.y * d1.y + f3.x * d1.z + f3.y * d1.w;
        #pragma unroll
        for (int o = 16; o > 0; o >>= 1) {
            ss += __shfl_down_sync(0xffffffffu, ss, o);
            tt += __shfl_down_sync(0xffffffffu, tt, o);
        }
        if (lane == 0) { s[node] = ss; t[node] = tt; }
    }
}

// ---------------- single-pass softmax aggregation (2-way edge unroll) -------
__global__ void gat_agg_kernel(const __half* __restrict__ h,
                               const float* __restrict__ s,
                               const float* __restrict__ t,
                               const int* __restrict__ off,
                               const int* __restrict__ csrc,
                               const float* __restrict__ bias,
                               __half* __restrict__ out, int n)
{
    int gw   = (blockIdx.x * blockDim.x + threadIdx.x) >> 5;
    int nwp  = (gridDim.x * blockDim.x) >> 5;
    int lane = threadIdx.x & 31;
    float4 b0 = *(const float4*)(bias + lane * 8);
    float4 b1 = *(const float4*)(bias + lane * 8 + 4);

    for (int node = gw; node < n; node += nwp) {
        int beg = off[node], end = off[node + 1];
        float tv = t[node];
        float d = 0.f;
        float acc[8];
        #pragma unroll
        for (int q = 0; q < 8; q++) acc[q] = 0.f;

        int p = beg;
        for (; p + 2 <= end; p += 2) {
            int src0 = csrc[p];
            int src1 = csrc[p + 1];
            float e0 = s[src0] + tv;
            float e1 = s[src1] + tv;
            uint4 hv0 = *(const uint4*)(h + (size_t)src0 * CC + lane * 8);
            uint4 hv1 = *(const uint4*)(h + (size_t)src1 * CC + lane * 8);
            e0 = (e0 > 0.f) ? e0 : 0.2f * e0;
            e1 = (e1 > 0.f) ? e1 : 0.2f * e1;
            float w0 = __expf(e0);
            float w1 = __expf(e1);
            d += w0;
            d += w1;
            const __half2* hh0 = (const __half2*)&hv0;
            const __half2* hh1 = (const __half2*)&hv1;
            #pragma unroll
            for (int q = 0; q < 4; q++) {
                float2 f0 = __half22float2(hh0[q]);
                acc[2 * q]     += w0 * f0.x;
                acc[2 * q + 1] += w0 * f0.y;
            }
            #pragma unroll
            for (int q = 0; q < 4; q++) {
                float2 f1 = __half22float2(hh1[q]);
                acc[2 * q]     += w1 * f1.x;
                acc[2 * q + 1] += w1 * f1.y;
            }
        }
        for (; p < end; ++p) {
            int src = csrc[p];
            float e = s[src] + tv;
            e = (e > 0.f) ? e : 0.2f * e;
            float w = __expf(e);
            d += w;
            uint4 hv = *(const uint4*)(h + (size_t)src * CC + lane * 8);
            const __half2* hh = (const __half2*)&hv;
            #pragma unroll
            for (int q = 0; q < 4; q++) {
                float2 f = __half22float2(hh[q]);
                acc[2 * q]     += w * f.x;
                acc[2 * q + 1] += w * f.y;
            }
        }

        float inv = 1.f / (d + 1e-16f);
        __half2 o_[4];
        o_[0] = __floats2half2_rn(acc[0] * inv + b0.x, acc[1] * inv + b0.y);
        o_[1] = __floats2half2_rn(acc[2] * inv + b0.z, acc[3] * inv + b0.w);
        o_[2] = __floats2half2_rn(acc[4] * inv + b1.x, acc[5] * inv + b1.y);
        o_[3] = __floats2half2_rn(acc[6] * inv + b1.z, acc[7] * inv + b1.w);
        *(uint4*)(out + (size_t)node * CC + lane * 8) = *(uint4*)o_;
    }
}

// ---------------- edge predictor over CSR (2-way edge unroll) ---------------
__global__ void edge_pred_csr_kernel(const __half* __restrict__ uv,
                                     const int* __restrict__ off,
                                     const int* __restrict__ csrc,
                                     const int* __restrict__ cedge,
                                     const float* __restrict__ bp1,
                                     const float* __restrict__ wp2,
                                     const float* __restrict__ bp2,
                                     float* __restrict__ out, int n)
{
    int gw   = (blockIdx.x * blockDim.x + threadIdx.x) >> 5;
    int nwp  = (gridDim.x * blockDim.x) >> 5;
    int lane = threadIdx.x & 31;
    float4 b0 = *(const float4*)(bp1 + lane * 8);
    float4 b1 = *(const float4*)(bp1 + lane * 8 + 4);
    float4 w0 = *(const float4*)(wp2 + lane * 8);
    float4 w1 = *(const float4*)(wp2 + lane * 8 + 4);
    float bb[8] = {b0.x, b0.y, b0.z, b0.w, b1.x, b1.y, b1.z, b1.w};
    float ww[8] = {w0.x, w0.y, w0.z, w0.w, w1.x, w1.y, w1.z, w1.w};
    float bias2 = bp2[0];

    for (int node = gw; node < n; node += nwp) {
        int beg = off[node] + 1;          // skip self-loop slot
        int end = off[node + 1];
        if (beg >= end) continue;
        uint4 vv = *(const uint4*)(uv + (size_t)node * 512 + 256 + lane * 8);
        const __half2* v2 = (const __half2*)&vv;
        float fvb[8];
        #pragma unroll
        for (int q = 0; q < 4; q++) {
            float2 f = __half22float2(v2[q]);
            fvb[2 * q]     = f.x + bb[2 * q];
            fvb[2 * q + 1] = f.y + bb[2 * q + 1];
        }
        int p = beg;
        for (; p + 2 <= end; p += 2) {
            int src0 = csrc[p];
            int src1 = csrc[p + 1];
            int eid0 = cedge[p];
            int eid1 = cedge[p + 1];
            uint4 uu0 = *(const uint4*)(uv + (size_t)src0 * 512 + lane * 8);
            uint4 uu1 = *(const uint4*)(uv + (size_t)src1 * 512 + lane * 8);
            const __half2* u20 = (const __half2*)&uu0;
            const __half2* u21 = (const __half2*)&uu1;
            float s0 = 0.f, s1 = 0.f;
            #pragma unroll
            for (int q = 0; q < 4; q++) {
                float2 fu0 = __half22float2(u20[q]);
                float2 fu1 = __half22float2(u21[q]);
                s0 += fmaxf(fu0.x + fvb[2 * q], 0.f) * ww[2 * q]
                    + fmaxf(fu0.y + fvb[2 * q + 1], 0.f) * ww[2 * q + 1];
                s1 += fmaxf(fu1.x + fvb[2 * q], 0.f) * ww[2 * q]
                    + fmaxf(fu1.y + fvb[2 * q + 1], 0.f) * ww[2 * q + 1];
            }
            #pragma unroll
            for (int o = 16; o > 0; o >>= 1) {
                s0 += __shfl_down_sync(0xffffffffu, s0, o);
                s1 += __shfl_down_sync(0xffffffffu, s1, o);
            }
            if (lane == 0) { out[eid0] = s0 + bias2; out[eid1] = s1 + bias2; }
        }
        for (; p < end; ++p) {
            int src = csrc[p];
            int eid = cedge[p];
            uint4 uu = *(const uint4*)(uv + (size_t)src * 512 + lane * 8);
            const __half2* u2 = (const __half2*)&uu;
            float sum = 0.f;
            #pragma unroll
            for (int q = 0; q < 4; q++) {
                float2 fu = __half22float2(u2[q]);
                sum += fmaxf(fu.x + fvb[2 * q], 0.f) * ww[2 * q]
                     + fmaxf(fu.y + fvb[2 * q + 1], 0.f) * ww[2 * q + 1];
            }
            #pragma unroll
            for (int o = 16; o > 0; o >>= 1)
                sum += __shfl_down_sync(0xffffffffu, sum, o);
            if (lane == 0) out[eid] = sum + bias2;
        }
    }
}

// ---------------- host driver -----------------------------------------------
extern "C" void kernel_launch(void* const* d_in, const int* in_sizes, int n_in,
                              void* d_out, int out_size)
{
    const float* x      = (const float*)d_in[0];
    const int*   ei     = (const int*)  d_in[1];
    const float* W1     = (const float*)d_in[2];
    const float* a_src1 = (const float*)d_in[3];
    const float* a_dst1 = (const float*)d_in[4];
    const float* b1     = (const float*)d_in[5];
    const float* W2     = (const float*)d_in[6];
    const float* a_src2 = (const float*)d_in[7];
    const float* a_dst2 = (const float*)d_in[8];
    const float* b2     = (const float*)d_in[9];
    const float* Wp1    = (const float*)d_in[10];
    const float* bp1    = (const float*)d_in[11];
    const float* wp2    = (const float*)d_in[12];
    const float* bp2    = (const float*)d_in[13];
    float* out          = (float*)d_out;

    const int* esrc = ei;
    const int* edst = ei + EE;

    __half *hA, *hB, *hC, *hD, *uv, *Bf;
    float *s, *t;
    int *deg, *off, *cursor, *csrc, *cedge;
    cudaGetSymbolAddress((void**)&hA, g_hA);
    cudaGetSymbolAddress((void**)&hB, g_hB);
    cudaGetSymbolAddress((void**)&hC, g_hC);
    cudaGetSymbolAddress((void**)&hD, g_hD);
    cudaGetSymbolAddress((void**)&uv, g_uv);
    cudaGetSymbolAddress((void**)&Bf, g_Bf);
    cudaGetSymbolAddress((void**)&s,  g_s);
    cudaGetSymbolAddress((void**)&t,  g_t);
    cudaGetSymbolAddress((void**)&deg, g_deg);
    cudaGetSymbolAddress((void**)&off, g_off);
    cudaGetSymbolAddress((void**)&cursor, g_cursor);
    cudaGetSymbolAddress((void**)&csrc, g_csrc);
    cudaGetSymbolAddress((void**)&cedge, g_cedge);

    const int dynSmem = NSTG * STG_STAGE;   // 165888 bytes
    cudaFuncSetAttribute(mma_gemm_a32_kernel,
                         cudaFuncAttributeMaxDynamicSharedMemorySize, dynSmem);
    cudaFuncSetAttribute(mma_gemm_a16_kernel,
                         cudaFuncAttributeMaxDynamicSharedMemorySize, dynSmem);

    const int TPB = 256;
    const int GS_N = 888;
    const int MB = (NN + GBM - 1) / GBM;   // 391

    cudaMemsetAsync(deg, 0, NN * sizeof(int));

    // launch order: GEMM1 is the 3rd kernel launch; keep profiling in mind
    pack_count_kernel<<<PACK_BLOCKS + COUNT_BLOCKS, TPB>>>(W1, W2, Wp1, Bf,
                                                           edst, deg);              // 1
    scan_kernel<<<1, 1024>>>(deg, off, cursor, csrc, NN);                           // 2
    mma_gemm_a32_kernel<<<dim3(1, MB), 256, dynSmem>>>(x, Bf, hA, NN, 2048, 256);   // 3
    scatter_dots_kernel<<<SCAT_BLOCKS + DOTS_BLOCKS, TPB>>>(esrc, edst, cursor,
                                                            csrc, cedge, hA,
                                                            a_src1, a_dst1, s, t);  // 4
    gat_agg_kernel<<<GS_N, TPB>>>(hA, s, t, off, csrc, b1, hB, NN);                 // 5

    // ---- layer 2 ----
    mma_gemm_a16_kernel<<<dim3(1, MB), 256, dynSmem>>>(hB, Bf + BF_W2_OFF, hC,
                                                       NN, 256, 256);               // 6
    node_dots_kernel<<<GS_N, TPB>>>(hC, a_src2, a_dst2, s, t, NN);                  // 7
    gat_agg_kernel<<<GS_N, TPB>>>(hC, s, t, off, csrc, b2, hD, NN);                 // 8

    // ---- edge predictor: [u | v] = h2 @ [Wp1_top | Wp1_bot] (N=512) ----
    mma_gemm_a16_kernel<<<dim3(2, MB), 256, dynSmem>>>(hD, Bf + BF_WP_OFF, uv,
                                                       NN, 256, 512);               // 9
    edge_pred_csr_kernel<<<GS_N, TPB>>>(uv, off, csrc, cedge, bp1, wp2, bp2,
                                        out, NN);                                   // 10
}